// round 1
// baseline (speedup 1.0000x reference)
#include <cuda_runtime.h>

// fired[b,s,r] = prod over universes of x[b,s, mf_index(r,u)]
// 3 universes x 5 MFs: r = i*25 + j*5 + k  ->  x[...,i]*x[...,5+j]*x[...,10+k]
// Exact zeros in x act as multiplicative identity (reference: where(rpu==0,1,rpu)).

static constexpr int F = 15;   // total membership functions
static constexpr int R = 125;  // rules

__global__ void __launch_bounds__(128, 16)
rules_fire_kernel(const float* __restrict__ x, float* __restrict__ out)
{
    __shared__ float sx[16];
    const int pos = blockIdx.x;          // 0 .. B*S-1
    const int t   = threadIdx.x;

    if (t < F) {
        float v = x[(long long)pos * F + t];
        // jnp.where(rpu == 0, 1, rpu): exact zero membership acts as identity
        sx[t] = (v == 0.0f) ? 1.0f : v;
    }
    __syncthreads();

    if (t < R) {
        const int i = t / 25;
        const int j = (t / 5) % 5;
        const int k = t % 5;
        out[(long long)pos * R + t] = sx[i] * sx[5 + j] * sx[10 + k];
    }
}

extern "C" void kernel_launch(void* const* d_in, const int* in_sizes, int n_in,
                              void* d_out, int out_size)
{
    const float* x = (const float*)d_in[0];   // (B, S, 15) float32
    float* out = (float*)d_out;               // (B, S, 125) float32

    const int npos = in_sizes[0] / F;         // B*S = 32768
    rules_fire_kernel<<<npos, 128>>>(x, out);
}

// round 2
// speedup vs baseline: 2.0500x; 2.0500x over previous
#include <cuda_runtime.h>

// fired[b,s,r] = x[...,i] * x[...,5+j] * x[...,10+k],  r = i*25 + j*5 + k
// Exact zeros in x act as multiplicative identity (reference: where(rpu==0,1,rpu)).
//
// R1 lesson: 32768 tiny CTAs -> ~14 waves -> wave-transition bound (~18us of the
// 21us). R2: single-wave launch. 1024 CTAs x 256 threads, 32 positions per CTA,
// float4 loads + float4 coalesced stores.

static constexpr int F  = 15;            // membership functions per position
static constexpr int R  = 125;           // rules per position
static constexpr int G  = 32;            // positions per block
static constexpr int NLD4 = G * F / 4;   // 120 float4 input loads per block
static constexpr int NV4  = G * R / 4;   // 1000 float4 outputs per block

__global__ void __launch_bounds__(256, 8)
rules_fire_v2(const float4* __restrict__ x4, float4* __restrict__ out4)
{
    __shared__ float sx[G * F];          // 480 floats, stride 15 (odd -> conflict-free)

    const int grp = blockIdx.x;
    const int t   = threadIdx.x;

    // Phase 1: stage this block's 32x15 inputs, zero->1 fix at load.
    if (t < NLD4) {
        float4 v = x4[(size_t)grp * NLD4 + t];
        v.x = (v.x == 0.0f) ? 1.0f : v.x;
        v.y = (v.y == 0.0f) ? 1.0f : v.y;
        v.z = (v.z == 0.0f) ? 1.0f : v.z;
        v.w = (v.w == 0.0f) ? 1.0f : v.w;
        reinterpret_cast<float4*>(sx)[t] = v;
    }
    __syncthreads();

    // Phase 2: 1000 float4 outputs per block; thread t does m = t, t+256, ...
    #pragma unroll
    for (int m = t; m < NV4; m += 256) {
        const int o = 4 * m;             // first of 4 consecutive output floats
        float4 res;
        float* pr = &res.x;
        #pragma unroll
        for (int e = 0; e < 4; e++) {
            const int oo = o + e;
            const int p  = oo / R;       // local position 0..31
            const int rr = oo - p * R;   // rule 0..124
            const int q  = rr / 5;
            const int k  = rr - q * 5;
            const int i  = q / 5;
            const int j  = q - i * 5;
            const float* row = sx + p * F;
            pr[e] = row[i] * row[5 + j] * row[10 + k];
        }
        out4[(size_t)grp * NV4 + m] = res;
    }
}

// Scalar tail for npos not divisible by G (not hit for B=16,S=2048, kept for safety).
__global__ void rules_fire_tail(const float* __restrict__ x, float* __restrict__ out,
                                int pos0, int npos)
{
    const int pos = pos0 + blockIdx.x;
    if (pos >= npos) return;
    __shared__ float sx[F + 1];
    const int t = threadIdx.x;
    if (t < F) {
        float v = x[(size_t)pos * F + t];
        sx[t] = (v == 0.0f) ? 1.0f : v;
    }
    __syncthreads();
    if (t < R) {
        const int i = t / 25, j = (t / 5) % 5, k = t % 5;
        out[(size_t)pos * R + t] = sx[i] * sx[5 + j] * sx[10 + k];
    }
}

extern "C" void kernel_launch(void* const* d_in, const int* in_sizes, int n_in,
                              void* d_out, int out_size)
{
    const float* x = (const float*)d_in[0];   // (B, S, 15) float32
    float* out = (float*)d_out;               // (B, S, 125) float32

    const int npos    = in_sizes[0] / F;      // 32768
    const int ngroups = npos / G;             // 1024
    if (ngroups > 0)
        rules_fire_v2<<<ngroups, 256>>>((const float4*)x, (float4*)out);

    const int tail = npos - ngroups * G;
    if (tail > 0)
        rules_fire_tail<<<tail, 128>>>(x, out, ngroups * G, npos);
}

// round 3
// speedup vs baseline: 2.3513x; 1.1470x over previous
#include <cuda_runtime.h>

// fired[b,s,r] = x[...,i] * x[...,5+j] * x[...,10+k],  r = i*25 + j*5 + k
// Exact zeros in x act as multiplicative identity (reference: where(rpu==0,1,rpu)).
//
// R2 lesson: issue-bound (78%) on index ALU (~8 IMAD per output element).
// R3: lcm(125,4)=500 floats = 4 positions ("superpos") = 125 float4s.
//     Thread t owns chunk c=t%125 of a superpos -> its rule decomposition is
//     FIXED. Precompute 12 smem pointers once; fully-unrolled loop over 4
//     superpos iterations -> body is 12 LDS + 8 FMUL + 1 STG.128 only.

static constexpr int F    = 15;           // membership functions per position
static constexpr int R    = 125;          // rules per position
static constexpr int G    = 32;           // positions per block
static constexpr int NLD4 = G * F / 4;    // 120 float4 input loads per block
static constexpr int SPF  = 4 * F;        // floats per superpos in sx (60)
static constexpr int NV4B = G * R / 4;    // 1000 float4 outputs per block

__global__ void __launch_bounds__(256, 8)
rules_fire_v3(const float4* __restrict__ x4, float4* __restrict__ out4)
{
    __shared__ float sx[G * F];           // 480 floats

    const int grp = blockIdx.x;
    const int t   = threadIdx.x;

    // Phase 1: stage 32x15 inputs, zero->1 fix at load.
    if (t < NLD4) {
        float4 v = x4[(size_t)grp * NLD4 + t];
        v.x = (v.x == 0.0f) ? 1.0f : v.x;
        v.y = (v.y == 0.0f) ? 1.0f : v.y;
        v.z = (v.z == 0.0f) ? 1.0f : v.z;
        v.w = (v.w == 0.0f) ? 1.0f : v.w;
        reinterpret_cast<float4*>(sx)[t] = v;
    }
    __syncthreads();

    // Phase 2: 250 active threads. c = chunk within superpos (fixed), sq = which
    // of 2 concurrent superpos. 8 superpos per block -> 4 unrolled iterations.
    if (t < 250) {
        const int c  = t % 125;
        const int sq = t / 125;

        // Precompute the 12 factor pointers ONCE (indices are loop-invariant).
        const float* p[4][3];
        #pragma unroll
        for (int e = 0; e < 4; e++) {
            const int u  = 4 * c + e;       // float index within superpos [0,500)
            const int pu = u / R;           // position within superpos 0..3
            const int rr = u - pu * R;      // rule 0..124
            const int i  = rr / 25;
            const int j  = (rr / 5) % 5;
            const int k  = rr % 5;
            const float* row = sx + sq * SPF + pu * F;
            p[e][0] = row + i;
            p[e][1] = row + 5 + j;
            p[e][2] = row + 10 + k;
        }

        float4* o = out4 + (size_t)grp * NV4B + sq * 125 + c;

        #pragma unroll
        for (int it = 0; it < 4; it++) {
            const int so = it * 2 * SPF;    // smem stride: 2 superpos per iter
            float4 res;
            res.x = p[0][0][so] * p[0][1][so] * p[0][2][so];
            res.y = p[1][0][so] * p[1][1][so] * p[1][2][so];
            res.z = p[2][0][so] * p[2][1][so] * p[2][2][so];
            res.w = p[3][0][so] * p[3][1][so] * p[3][2][so];
            o[it * 250] = res;              // 2 superpos x 125 float4 per iter
        }
    }
}

// Scalar fallback for npos not divisible by G (not hit for B=16,S=2048).
__global__ void rules_fire_tail(const float* __restrict__ x, float* __restrict__ out,
                                int pos0, int npos)
{
    const int pos = pos0 + blockIdx.x;
    if (pos >= npos) return;
    __shared__ float sxt[F + 1];
    const int t = threadIdx.x;
    if (t < F) {
        float v = x[(size_t)pos * F + t];
        sxt[t] = (v == 0.0f) ? 1.0f : v;
    }
    __syncthreads();
    if (t < R) {
        const int i = t / 25, j = (t / 5) % 5, k = t % 5;
        out[(size_t)pos * R + t] = sxt[i] * sxt[5 + j] * sxt[10 + k];
    }
}

extern "C" void kernel_launch(void* const* d_in, const int* in_sizes, int n_in,
                              void* d_out, int out_size)
{
    const float* x = (const float*)d_in[0];   // (B, S, 15) float32
    float* out = (float*)d_out;               // (B, S, 125) float32

    const int npos    = in_sizes[0] / F;      // 32768
    const int ngroups = npos / G;             // 1024
    if (ngroups > 0)
        rules_fire_v3<<<ngroups, 256>>>((const float4*)x, (float4*)out);

    const int tail = npos - ngroups * G;
    if (tail > 0)
        rules_fire_tail<<<tail, 128>>>(x, out, ngroups * G, npos);
}

// round 4
// speedup vs baseline: 2.3597x; 1.0036x over previous
#include <cuda_runtime.h>

// fired[b,s,r] = x[...,i] * x[...,5+j] * x[...,10+k],  r = i*25 + j*5 + k
// Exact zeros in x act as identity (reference: where(rpu==0,1,rpu)).
//
// R3 lesson: pointer-array smem access bloated SASS ~4x (generic LD suspected);
// kernel is latency-bound. R4: int-offset LDS + ab-factorization:
//   phase 1b: ab[p][i*5+j] = a[i]*b[j]   (25 vals) + c[p][5] in a 33-float row
//   phase 2 : out = ab[rr/5] * c[rr%5]   -> 8 LDS + 4 FMUL + 1 STG.128 / float4
// Multiplication order (a*b)*c matches jnp.prod reduce order; 1-identities exact.

static constexpr int F    = 15;           // membership functions per position
static constexpr int R    = 125;          // rules per position
static constexpr int G    = 32;           // positions per block
static constexpr int NLD4 = G * F / 4;    // 120 float4 input loads per block
static constexpr int NV4B = G * R / 4;    // 1000 float4 outputs per block
static constexpr int PSTR = 33;           // padded row stride in sbuf (bank-safe)

__global__ void __launch_bounds__(256, 8)
rules_fire_v4(const float4* __restrict__ x4, float4* __restrict__ out4)
{
    __shared__ float sraw[G * F];         // 480: raw (zero-fixed) membership rows
    __shared__ float sbuf[G * PSTR];      // per pos: [0,25)=ab products, [25,30)=c

    const int grp = blockIdx.x;
    const int t   = threadIdx.x;

    // Phase 1: stage 32x15 inputs, zero->1 fix at load.
    if (t < NLD4) {
        float4 v = x4[(size_t)grp * NLD4 + t];
        v.x = (v.x == 0.0f) ? 1.0f : v.x;
        v.y = (v.y == 0.0f) ? 1.0f : v.y;
        v.z = (v.z == 0.0f) ? 1.0f : v.z;
        v.w = (v.w == 0.0f) ? 1.0f : v.w;
        reinterpret_cast<float4*>(sraw)[t] = v;
    }
    __syncthreads();

    // Phase 1b: 160 threads: thread (p, i) builds ab row i and copies one c.
    if (t < 160) {
        const int p = t / 5;
        const int i = t % 5;
        const int rb  = p * F;            // raw row base
        const int bb  = p * PSTR;         // sbuf row base
        const float a = sraw[rb + i];
        #pragma unroll
        for (int j = 0; j < 5; j++)
            sbuf[bb + i * 5 + j] = a * sraw[rb + 5 + j];
        sbuf[bb + 25 + i] = sraw[rb + 10 + i];   // copy c[i]
    }
    __syncthreads();

    // Phase 2: 250 threads. c = float4 chunk within a 500-float superpos (fixed
    // -> rule decomposition fixed); sq = which of 2 concurrent superpos.
    if (t < 250) {
        const int c  = t % 125;
        const int sq = t / 125;

        // Loop-invariant int offsets into sbuf (clean LDS, stride folds to imm).
        int off_ab[4], off_c[4];
        #pragma unroll
        for (int e = 0; e < 4; e++) {
            const int u  = 4 * c + e;          // float index within superpos
            const int pu = u / R;              // position within superpos 0..3
            const int rr = u - pu * R;         // rule 0..124
            const int bb = (sq * 4 + pu) * PSTR;
            off_ab[e] = bb + rr / 5;           // ab[i*5+j]
            off_c [e] = bb + 25 + rr % 5;      // c[k]
        }

        float4* o = out4 + (size_t)grp * NV4B + sq * 125 + c;

        #pragma unroll
        for (int it = 0; it < 4; it++) {
            const int so = it * 8 * PSTR;      // 8 positions (2 superpos) per iter
            float4 res;
            res.x = sbuf[off_ab[0] + so] * sbuf[off_c[0] + so];
            res.y = sbuf[off_ab[1] + so] * sbuf[off_c[1] + so];
            res.z = sbuf[off_ab[2] + so] * sbuf[off_c[2] + so];
            res.w = sbuf[off_ab[3] + so] * sbuf[off_c[3] + so];
            o[it * 250] = res;                 // 2 superpos x 125 float4 / iter
        }
    }
}

// Scalar fallback for npos not divisible by G (not hit for B=16,S=2048).
__global__ void rules_fire_tail(const float* __restrict__ x, float* __restrict__ out,
                                int pos0, int npos)
{
    const int pos = pos0 + blockIdx.x;
    if (pos >= npos) return;
    __shared__ float sxt[F + 1];
    const int t = threadIdx.x;
    if (t < F) {
        float v = x[(size_t)pos * F + t];
        sxt[t] = (v == 0.0f) ? 1.0f : v;
    }
    __syncthreads();
    if (t < R) {
        const int i = t / 25, j = (t / 5) % 5, k = t % 5;
        out[(size_t)pos * R + t] = sxt[i] * sxt[5 + j] * sxt[10 + k];
    }
}

extern "C" void kernel_launch(void* const* d_in, const int* in_sizes, int n_in,
                              void* d_out, int out_size)
{
    const float* x = (const float*)d_in[0];   // (B, S, 15) float32
    float* out = (float*)d_out;               // (B, S, 125) float32

    const int npos    = in_sizes[0] / F;      // 32768
    const int ngroups = npos / G;             // 1024
    if (ngroups > 0)
        rules_fire_v4<<<ngroups, 256>>>((const float4*)x, (float4*)out);

    const int tail = npos - ngroups * G;
    if (tail > 0)
        rules_fire_tail<<<tail, 128>>>(x, out, ngroups * G, npos);
}